// round 14
// baseline (speedup 1.0000x reference)
#include <cuda_runtime.h>
#include <cstdint>

#define PI_F 3.14159265358979f

// ---------------- device-global tables (prep -> main) ----------------
__device__ float d_B1f[8192];   // B1[64k][128n] in mma B-frag layout, tf32
__device__ float d_Wqf[4096];   // Wq'[64k][64n] in mma B-frag layout, tf32

__device__ __forceinline__ uint32_t f2tf32(float f) {
    uint32_t r;
    asm("cvt.rna.tf32.f32 %0, %1;" : "=r"(r) : "f"(f));
    return r;
}

__device__ __forceinline__ void mma8(float* d, const uint32_t* a, const uint32_t* b) {
    asm volatile(
        "mma.sync.aligned.m16n8k8.row.col.f32.tf32.tf32.f32 "
        "{%0,%1,%2,%3}, {%4,%5,%6,%7}, {%8,%9}, {%0,%1,%2,%3};"
        : "+f"(d[0]), "+f"(d[1]), "+f"(d[2]), "+f"(d[3])
        : "r"(a[0]), "r"(a[1]), "r"(a[2]), "r"(a[3]), "r"(b[0]), "r"(b[1]));
}

// B-fragment storage index (float units) for element (k, n)
__device__ __forceinline__ int fidxB1(int k, int n) {   // 16 n-tiles
    return ((((k >> 3) * 16 + (n >> 3)) * 32 + (n & 7) * 4 + (k & 3)) << 1) + ((k >> 2) & 1);
}
__device__ __forceinline__ int fidxWq(int k, int n) {   // 8 n-tiles
    return ((((k >> 3) * 8 + (n >> 3)) * 32 + (n & 7) * 4 + (k & 3)) << 1) + ((k >> 2) & 1);
}

// ---------------- quantum gate helpers (2-state ILP, prep only) ----------------
__device__ __forceinline__ void gate_b5_2(const float2* G,
                                          float* a0r, float* a0i, float* a1r, float* a1i) {
    float2 g00 = G[0], g01 = G[1], g10 = G[2], g11 = G[3];
#pragma unroll
    for (int j = 0; j < 2; j++) {
        float n0r = g00.x * a0r[j] - g00.y * a0i[j] + g01.x * a1r[j] - g01.y * a1i[j];
        float n0i = g00.x * a0i[j] + g00.y * a0r[j] + g01.x * a1i[j] + g01.y * a1r[j];
        float n1r = g10.x * a0r[j] - g10.y * a0i[j] + g11.x * a1r[j] - g11.y * a1i[j];
        float n1i = g10.x * a0i[j] + g10.y * a0r[j] + g11.x * a1i[j] + g11.y * a1r[j];
        a0r[j] = n0r; a0i[j] = n0i; a1r[j] = n1r; a1i[j] = n1i;
    }
}

__device__ __forceinline__ void gate_lo_2(int bbit, int lane, const float2* G,
                                          float* a0r, float* a0i, float* a1r, float* a1i) {
    const unsigned F = 0xffffffffu;
    float2 g00 = G[0], g01 = G[1], g10 = G[2], g11 = G[3];
    int m = 1 << bbit;
    bool hi = (lane >> bbit) & 1;
    float Ar = hi ? g11.x : g00.x, Ai = hi ? g11.y : g00.y;
    float Pr = hi ? g10.x : g01.x, Pi = hi ? g10.y : g01.y;
#pragma unroll
    for (int j = 0; j < 2; j++) {
        float p0r = __shfl_xor_sync(F, a0r[j], m);
        float p0i = __shfl_xor_sync(F, a0i[j], m);
        float p1r = __shfl_xor_sync(F, a1r[j], m);
        float p1i = __shfl_xor_sync(F, a1i[j], m);
        float n0r = Ar * a0r[j] - Ai * a0i[j] + Pr * p0r - Pi * p0i;
        float n0i = Ar * a0i[j] + Ai * a0r[j] + Pr * p0i + Pi * p0r;
        float n1r = Ar * a1r[j] - Ai * a1i[j] + Pr * p1r - Pi * p1i;
        float n1i = Ar * a1i[j] + Ai * a1r[j] + Pr * p1i + Pi * p1r;
        a0r[j] = n0r; a0i[j] = n0i; a1r[j] = n1r; a1i[j] = n1i;
    }
}

__device__ __forceinline__ int ring_src(int s) {
    int b5 = (s >> 5) & 1, b4 = (s >> 4) & 1, b3 = (s >> 3) & 1;
    int b2 = (s >> 2) & 1, b1 = (s >> 1) & 1, b0 = s & 1;
    b5 ^= b0; b0 ^= b1; b1 ^= b2; b2 ^= b3; b3 ^= b4; b4 ^= b5;
    return (b5 << 5) | (b4 << 4) | (b3 << 3) | (b2 << 2) | (b1 << 1) | b0;
}

__device__ __forceinline__ void ring2_2(int q0l, int q0h, int q1l, int q1h,
                                        float* a0r, float* a0i, float* a1r, float* a1i) {
    const unsigned F = 0xffffffffu;
#pragma unroll
    for (int j = 0; j < 2; j++) {
        float x0r = __shfl_sync(F, a0r[j], q0l);
        float y0r = __shfl_sync(F, a1r[j], q0l);
        float x0i = __shfl_sync(F, a0i[j], q0l);
        float y0i = __shfl_sync(F, a1i[j], q0l);
        float x1r = __shfl_sync(F, a0r[j], q1l);
        float y1r = __shfl_sync(F, a1r[j], q1l);
        float x1i = __shfl_sync(F, a0i[j], q1l);
        float y1i = __shfl_sync(F, a1i[j], q1l);
        a0r[j] = q0h ? y0r : x0r; a0i[j] = q0h ? y0i : x0i;
        a1r[j] = q1h ? y1r : x1r; a1i[j] = q1h ? y1i : x1i;
    }
}

// ---------------- prep: circuit unitary B1 + Wq' (overlapped via PDL) ----------------
__global__ void k_prep(const float* __restrict__ qcnn, const float* __restrict__ meas,
                       const float* __restrict__ ow) {
    cudaTriggerProgrammaticLaunchCompletion();

    __shared__ float2 s_g1[6][4], s_g2[6][4];
    __shared__ float s_b0[6];
    int tid = threadIdx.x, lane = tid & 31, warp = tid >> 5;

    if (tid < 6) {
        int i = tid;
        float b0 = qcnn[i * 6 + 3];
        s_b0[i] = b0;
        float a1 = qcnn[36 + i * 6];
        float b1 = qcnn[36 + i * 6 + 3];
        float ca = cosf(0.5f * a1), sa = sinf(0.5f * a1);
        float cb = cosf(0.5f * b1), sbv = sinf(0.5f * b1);
        s_g1[i][0] = make_float2(cb * ca, -sbv * ca);
        s_g1[i][1] = make_float2(-cb * sa, sbv * sa);
        s_g1[i][2] = make_float2(cb * sa, sbv * sa);
        s_g1[i][3] = make_float2(cb * ca, sbv * ca);
        float th = meas[i * 3 + 0], phv = meas[i * 3 + 1], la = meas[i * 3 + 2];
        float ct = cosf(0.5f * th), st = sinf(0.5f * th);
        s_g2[i][0] = make_float2(ct, 0.f);
        s_g2[i][1] = make_float2(-cosf(la) * st, -sinf(la) * st);
        s_g2[i][2] = make_float2(cosf(phv) * st, sinf(phv) * st);
        s_g2[i][3] = make_float2(cosf(phv + la) * ct, sinf(phv + la) * ct);
    }
    __syncthreads();

    int q0 = ring_src(lane), q1 = ring_src(lane + 32);
    int q0l = q0 & 31, q0h = q0 >> 5;
    int q1l = q1 & 31, q1h = q1 >> 5;

    for (int q = 0; q < 4; q++) {
        int tcol[2] = {(warp * 4 + q) * 2, (warp * 4 + q) * 2 + 1};
        float a0r[2], a0i[2], a1r[2], a1i[2];
#pragma unroll
        for (int j = 0; j < 2; j++) {
            float th = 0.f;
#pragma unroll
            for (int i = 0; i < 6; i++)
                if ((tcol[j] >> (5 - i)) & 1) th += s_b0[i];
            float sv, cv;
            __sincosf(th, &sv, &cv);
            a0r[j] = (lane == tcol[j]) ? cv : 0.f;
            a0i[j] = (lane == tcol[j]) ? sv : 0.f;
            a1r[j] = (lane + 32 == tcol[j]) ? cv : 0.f;
            a1i[j] = (lane + 32 == tcol[j]) ? sv : 0.f;
        }
        ring2_2(q0l, q0h, q1l, q1h, a0r, a0i, a1r, a1i);
#pragma unroll
        for (int i = 0; i < 6; i++) {
            if (i == 0) gate_b5_2(s_g1[0], a0r, a0i, a1r, a1i);
            else        gate_lo_2(5 - i, lane, s_g1[i], a0r, a0i, a1r, a1i);
        }
        ring2_2(q0l, q0h, q1l, q1h, a0r, a0i, a1r, a1i);
#pragma unroll
        for (int i = 0; i < 6; i++) {
            if (i == 0) gate_b5_2(s_g2[0], a0r, a0i, a1r, a1i);
            else        gate_lo_2(5 - i, lane, s_g2[i], a0r, a0i, a1r, a1i);
        }
#pragma unroll
        for (int j = 0; j < 2; j++) {
            int k = tcol[j];
            d_B1f[fidxB1(k, lane)]          = __uint_as_float(f2tf32(a0r[j]));
            d_B1f[fidxB1(k, 64 + lane)]     = __uint_as_float(f2tf32(a0i[j]));
            d_B1f[fidxB1(k, lane + 32)]     = __uint_as_float(f2tf32(a1r[j]));
            d_B1f[fidxB1(k, 96 + lane)]     = __uint_as_float(f2tf32(a1i[j]));
        }
    }
    for (int i = tid; i < 4096; i += 256) {
        int s = i >> 6, co = i & 63;
        float acc = 0.f;
#pragma unroll
        for (int w = 0; w < 6; w++)
            acc += ow[co * 6 + w] * (((s >> (5 - w)) & 1) ? -1.f : 1.f);
        d_Wqf[fidxWq(s, co)] = __uint_as_float(f2tf32(acc));
    }
}

// ---------------- fused kernel ----------------
// 256 CTAs x 128 thr (4 warps). CTA = 128 px x 72 outputs. K=576, 8 chunks.
// Warp w owns TWO m-tiles: mt=w (rows 0) and mt=w+4 (row 1); B frags reused x2.
// dyn smem: mainloop [xs 8448 | smB 20736]; tail: [stg 33280 @0 | PSI @33280]
#define SMB_OFF 8448
#define PSI_OFF 33280
#define FUSED_SMEM 66560

__global__ __launch_bounds__(128, 3) void k_fused(
    const float* __restrict__ x, const float* __restrict__ wr,
    const float* __restrict__ wd, const float* __restrict__ rb,
    const float* __restrict__ db, const float* __restrict__ style,
    const float* __restrict__ sw, const float* __restrict__ sb,
    const float* __restrict__ qcnn, const float* __restrict__ ob,
    float* __restrict__ out) {
    extern __shared__ char smem[];
    uint32_t* xs_u = (uint32_t*)smem;                  // x tile, tf32 bits, linear 2112
    char* smB = smem + SMB_OFF;                        // B frags [kt][nt][lane] uint2
    __shared__ float s_phiadd[6];
    __shared__ float2 scs[8][96];                      // [mtile][px*6+wire]
    __shared__ float sphi_all[8][96];                  // [mtile][16 px][6 wires]

    const unsigned F = 0xffffffffu;
    int tid = threadIdx.x;
    int lane = tid & 31;
    int wid = tid >> 5;               // 0..3
    int g = lane >> 2, t4 = lane & 3;
    int px0 = blockIdx.x << 7;
    int b = px0 >> 12;
    int hwbase = px0 & 4095;
    int h0 = hwbase >> 6;

    // style projection: wires wid and wid+4 (wid<2)
    for (int wire = wid; wire < 6; wire += 4) {
        float4 a = reinterpret_cast<const float4*>(style + b * 128)[lane];
        float4 w = reinterpret_cast<const float4*>(sw + wire * 128)[lane];
        float acc0 = a.x * w.x + a.y * w.y + a.z * w.z + a.w * w.w;
#pragma unroll
        for (int o = 16; o; o >>= 1) acc0 += __shfl_xor_sync(F, acc0, o);
        if (lane == 0)
            s_phiadd[wire] = PI_F * tanhf(acc0 + sb[wire]) + qcnn[wire * 6];
    }

    // --- A-offset table (chunk-invariant) ---
    int offs[18];
#pragma unroll
    for (int kk2 = 0; kk2 < 18; kk2++) {
        int kt = kk2 >> 1, half = kk2 & 1;
        int kloc = kt * 8 + 4 * half + t4;
        int ci = kloc / 9, kr = kloc - ci * 9;
        offs[kk2] = ci * 264 + (kr / 3) * 66 + (kr - (kr / 3) * 3);
    }
    int base0 = wid * 16 + g;          // mt = wid (image row 0); mt+4 = +66

    float acc[2][9][4];
#pragma unroll
    for (int m = 0; m < 2; m++)
#pragma unroll
        for (int j = 0; j < 9; j++)
#pragma unroll
            for (int c = 0; c < 4; c++) acc[m][j][c] = 0.f;

    float px_x[17];

    // --- prefetch chunk 0 x-tile ---
#pragma unroll
    for (int it = 0; it < 17; it++) {
        int j = tid + (it << 7);
        float v = 0.f;
        if (it < 16 || tid < 64) {
            int ci = j / 264, rem = j - ci * 264;
            int r = rem / 66, cpos = rem - r * 66;
            int gh = h0 - 1 + r, gw = cpos - 1;
            if ((unsigned)gh < 64u && (unsigned)gw < 64u)
                v = __ldg(x + (((b << 6) + ci) << 12) + (gh << 6) + gw);
        }
        px_x[it] = v;
    }

    // --- pipelined mainloop ---
    for (int chunk = 0; chunk < 8; chunk++) {
        if (chunk) __syncthreads();
        // STS x from prefetch regs
#pragma unroll
        for (int it = 0; it < 17; it++) {
            if (it < 16 || tid < 64)
                xs_u[tid + (it << 7)] = f2tf32(px_x[it]);
        }
        // stage weights directly (L2-hot after chunk 0; cross-CTA overlap covers)
        for (int i = tid; i < 1260; i += 128) {
            int n = i / 18, qf = i - n * 18;
            const float* src = (n < 64) ? (wr + n * 576) : (wd + (n - 64) * 576);
            float4 v = *reinterpret_cast<const float4*>(src + chunk * 72 + (qf << 2));
            int kt = qf >> 1, half = qf & 1;
            uint32_t* dst = reinterpret_cast<uint32_t*>(smB) +
                            (((kt * 9 + (n >> 3)) * 32 + ((n & 7) << 2)) << 1) + half;
            dst[0] = f2tf32(v.x);
            dst[2] = f2tf32(v.y);
            dst[4] = f2tf32(v.z);
            dst[6] = f2tf32(v.w);
        }
        __syncthreads();
        // prefetch next chunk x (overlaps mma)
        if (chunk < 7) {
            int cn = chunk + 1;
#pragma unroll
            for (int it = 0; it < 17; it++) {
                int j = tid + (it << 7);
                float v = 0.f;
                if (it < 16 || tid < 64) {
                    int ci = j / 264, rem = j - ci * 264;
                    int r = rem / 66, cpos = rem - r * 66;
                    int gh = h0 - 1 + r, gw = cpos - 1;
                    if ((unsigned)gh < 64u && (unsigned)gw < 64u)
                        v = __ldg(x + (((b << 6) + (cn << 3) + ci) << 12) + (gh << 6) + gw);
                }
                px_x[it] = v;
            }
        }
        // mma phase: 2 m-tiles per warp, B loaded once per (kt, nt)
#pragma unroll
        for (int kt = 0; kt < 9; kt++) {
            uint32_t A0[4], A1[4];
            A0[0] = xs_u[offs[2 * kt] + base0];
            A0[1] = xs_u[offs[2 * kt] + base0 + 8];
            A0[2] = xs_u[offs[2 * kt + 1] + base0];
            A0[3] = xs_u[offs[2 * kt + 1] + base0 + 8];
            A1[0] = xs_u[offs[2 * kt] + base0 + 66];
            A1[1] = xs_u[offs[2 * kt] + base0 + 74];
            A1[2] = xs_u[offs[2 * kt + 1] + base0 + 66];
            A1[3] = xs_u[offs[2 * kt + 1] + base0 + 74];
#pragma unroll
            for (int nt = 0; nt < 9; nt++) {
                uint2 bb = *reinterpret_cast<const uint2*>(
                    smB + ((kt * 9 + nt) * 32 + lane) * 8);
                uint32_t B[2] = {bb.x, bb.y};
                mma8(acc[0][nt], A0, B);
                mma8(acc[1][nt], A1, B);
            }
        }
    }
    __syncthreads();   // mma done; mainloop smem regions reusable

    float* stg = (float*)smem;                         // [128][65]
    uint32_t* PSIu = (uint32_t*)(smem + PSI_OFF);      // [128][65]

    cudaGridDependencySynchronize();     // PDL: k_prep done before B1/Wq reads

    // --- tail: loop over the warp's 2 m-tiles ---
#pragma unroll 1
    for (int m = 0; m < 2; m++) {
        int mtile = wid + 4 * m;
        float* sphi = sphi_all[mtile];

        // phi staging + conv epilogue for this m-tile
        if (t4 < 3) {
#pragma unroll
            for (int c = 0; c < 4; c++) {
                int pxl = g + 8 * (c >> 1);
                int wire = 2 * t4 + (c & 1);
                sphi[pxl * 6 + wire] =
                    PI_F * tanhf(acc[m][8][c] + __ldg(db + wire)) + s_phiadd[wire];
            }
        }
#pragma unroll
        for (int nt = 0; nt < 8; nt++) {
#pragma unroll
            for (int c = 0; c < 4; c++) {
                int pxl = g + 8 * (c >> 1);
                int co = nt * 8 + 2 * t4 + (c & 1);
                stg[(mtile * 16 + pxl) * 65 + co] = acc[m][nt][c] + __ldg(rb + co);
            }
        }
        __syncwarp();

        // cos/sin(phi/2): 3 sincos per lane
#pragma unroll
        for (int r = 0; r < 3; r++) {
            int idx = lane + (r << 5);
            float ph = sphi[idx];
            float sv, cv;
            __sincosf(0.5f * ph, &sv, &cv);
            scs[mtile][idx] = make_float2(cv, sv);
        }
        __syncwarp();

        // real product state PSI[px][64]
        for (int pxl = 0; pxl < 16; pxl++) {
            float2 c0 = scs[mtile][pxl * 6 + 0];
            float mm = 1.f;
#pragma unroll
            for (int i = 1; i < 6; i++) {
                float2 ci = scs[mtile][pxl * 6 + i];
                mm *= ((lane >> (5 - i)) & 1) ? ci.y : ci.x;
            }
            int row = (mtile * 16 + pxl) * 65;
            PSIu[row + lane] = f2tf32(c0.x * mm);
            PSIu[row + lane + 32] = f2tf32(c0.y * mm);
        }
        __syncwarp();

        // GEMM1: D1[px][128] = PSI x B1 (B frags from L2)
        float acc1[16][4];
#pragma unroll
        for (int j = 0; j < 16; j++)
#pragma unroll
            for (int c = 0; c < 4; c++) acc1[j][c] = 0.f;
        {
            int abase = (mtile * 16 + g) * 65 + t4;
#pragma unroll
            for (int kt = 0; kt < 8; kt++) {
                uint32_t A[4];
                A[0] = PSIu[abase + kt * 8];
                A[1] = PSIu[abase + kt * 8 + 8 * 65];
                A[2] = PSIu[abase + kt * 8 + 4];
                A[3] = PSIu[abase + kt * 8 + 4 + 8 * 65];
#pragma unroll
                for (int nt = 0; nt < 16; nt++) {
                    uint2 bb = *reinterpret_cast<const uint2*>(
                        d_B1f + (((kt * 16 + nt) * 32 + lane) << 1));
                    uint32_t B[2] = {bb.x, bb.y};
                    mma8(acc1[nt], A, B);
                }
            }
        }
        // probs into PSI region (own rows only)
#pragma unroll
        for (int nt = 0; nt < 8; nt++) {
#pragma unroll
            for (int c = 0; c < 4; c++) {
                float p = acc1[nt][c] * acc1[nt][c] + acc1[nt + 8][c] * acc1[nt + 8][c];
                int s = nt * 8 + 2 * t4 + (c & 1);
                int pxg = mtile * 16 + g + 8 * (c >> 1);
                PSIu[pxg * 65 + s] = f2tf32(p);
            }
        }
        __syncwarp();

        // GEMM2: D2[px][64co] = p x Wq' (B frags from L2)
        float acc2[8][4];
#pragma unroll
        for (int j = 0; j < 8; j++)
#pragma unroll
            for (int c = 0; c < 4; c++) acc2[j][c] = 0.f;
        {
            int abase = (mtile * 16 + g) * 65 + t4;
#pragma unroll
            for (int kt = 0; kt < 8; kt++) {
                uint32_t A[4];
                A[0] = PSIu[abase + kt * 8];
                A[1] = PSIu[abase + kt * 8 + 8 * 65];
                A[2] = PSIu[abase + kt * 8 + 4];
                A[3] = PSIu[abase + kt * 8 + 4 + 8 * 65];
#pragma unroll
                for (int nt = 0; nt < 8; nt++) {
                    uint2 bb = *reinterpret_cast<const uint2*>(
                        d_Wqf + (((kt * 8 + nt) * 32 + lane) << 1));
                    uint32_t B[2] = {bb.x, bb.y};
                    mma8(acc2[nt], A, B);
                }
            }
        }
        // merge quant output + bias into stg
#pragma unroll
        for (int nt = 0; nt < 8; nt++) {
#pragma unroll
            for (int c = 0; c < 4; c++) {
                int co = nt * 8 + 2 * t4 + (c & 1);
                int pxg = mtile * 16 + g + 8 * (c >> 1);
                stg[pxg * 65 + co] += acc2[nt][c] + __ldg(ob + co);
            }
        }
        __syncwarp();
    }
    __syncthreads();

    // --- fully coalesced final write ---
    for (int i = tid; i < 8192; i += 128) {
        int co = i >> 7, px = i & 127;
        out[(((b << 6) + co) << 12) + hwbase + px] = stg[px * 65 + co];
    }
}

// ---------------- launch ----------------
extern "C" void kernel_launch(void* const* d_in, const int* in_sizes, int n_in,
                              void* d_out, int out_size) {
    const float* x     = (const float*)d_in[0];
    const float* style = (const float*)d_in[1];
    const float* wd    = (const float*)d_in[2];   // data_proj_w [6,576]
    const float* db    = (const float*)d_in[3];   // data_proj_b [6]
    const float* sw    = (const float*)d_in[4];   // style_to_data_w [6,128]
    const float* sb    = (const float*)d_in[5];   // style_to_data_b [6]
    const float* qcnn  = (const float*)d_in[6];   // [2,6,2,3]
    const float* meas  = (const float*)d_in[7];   // [6,3]
    const float* ow    = (const float*)d_in[8];   // out_proj_w [64,6]
    const float* ob    = (const float*)d_in[9];   // out_proj_b [64]
    const float* wr    = (const float*)d_in[10];  // res_proj_w [64,576]
    const float* rb    = (const float*)d_in[11];  // res_proj_b [64]
    float* out = (float*)d_out;

    cudaFuncSetAttribute(k_fused, cudaFuncAttributeMaxDynamicSharedMemorySize, FUSED_SMEM);

    k_prep<<<1, 256>>>(qcnn, meas, ow);

    // PDL: k_fused starts as soon as k_prep triggers launch completion (entry);
    // gates on k_prep's full completion only before the tail GEMMs.
    cudaLaunchConfig_t cfg = {};
    cfg.gridDim = dim3(256, 1, 1);
    cfg.blockDim = dim3(128, 1, 1);
    cfg.dynamicSmemBytes = FUSED_SMEM;
    cfg.stream = 0;
    cudaLaunchAttribute attrs[1];
    attrs[0].id = cudaLaunchAttributeProgrammaticStreamSerialization;
    attrs[0].val.programmaticStreamSerializationAllowed = 1;
    cfg.attrs = attrs;
    cfg.numAttrs = 1;
    cudaLaunchKernelEx(&cfg, k_fused, x, wr, wd, rb, db, style, sw, sb, qcnn, ob, out);
}

// round 15
// speedup vs baseline: 2.6445x; 2.6445x over previous
#include <cuda_runtime.h>
#include <cstdint>

#define PI_F 3.14159265358979f

// ---------------- device-global tables (prep -> main) ----------------
__device__ float d_B1f[8192];    // B1[64k][128n] in mma B-frag layout, tf32
__device__ float d_Wqf[4096];    // Wq'[64k][64n] in mma B-frag layout, tf32
__device__ float d_Wrf[41472];   // conv weights [8 chunk][9 kt][9 nt][32 lane][2]

__device__ __forceinline__ uint32_t f2tf32(float f) {
    uint32_t r;
    asm("cvt.rna.tf32.f32 %0, %1;" : "=r"(r) : "f"(f));
    return r;
}

__device__ __forceinline__ void mma8(float* d, const uint32_t* a, const uint32_t* b) {
    asm volatile(
        "mma.sync.aligned.m16n8k8.row.col.f32.tf32.tf32.f32 "
        "{%0,%1,%2,%3}, {%4,%5,%6,%7}, {%8,%9}, {%0,%1,%2,%3};"
        : "+f"(d[0]), "+f"(d[1]), "+f"(d[2]), "+f"(d[3])
        : "r"(a[0]), "r"(a[1]), "r"(a[2]), "r"(a[3]), "r"(b[0]), "r"(b[1]));
}

// B-fragment storage index (float units) for element (k, n)
__device__ __forceinline__ int fidxB1(int k, int n) {   // 16 n-tiles
    return ((((k >> 3) * 16 + (n >> 3)) * 32 + (n & 7) * 4 + (k & 3)) << 1) + ((k >> 2) & 1);
}
__device__ __forceinline__ int fidxWq(int k, int n) {   // 8 n-tiles
    return ((((k >> 3) * 8 + (n >> 3)) * 32 + (n & 7) * 4 + (k & 3)) << 1) + ((k >> 2) & 1);
}

// ---------------- quantum gate helpers (2-state ILP, prep only) ----------------
__device__ __forceinline__ void gate_b5_2(const float2* G,
                                          float* a0r, float* a0i, float* a1r, float* a1i) {
    float2 g00 = G[0], g01 = G[1], g10 = G[2], g11 = G[3];
#pragma unroll
    for (int j = 0; j < 2; j++) {
        float n0r = g00.x * a0r[j] - g00.y * a0i[j] + g01.x * a1r[j] - g01.y * a1i[j];
        float n0i = g00.x * a0i[j] + g00.y * a0r[j] + g01.x * a1i[j] + g01.y * a1r[j];
        float n1r = g10.x * a0r[j] - g10.y * a0i[j] + g11.x * a1r[j] - g11.y * a1i[j];
        float n1i = g10.x * a0i[j] + g10.y * a0r[j] + g11.x * a1i[j] + g11.y * a1r[j];
        a0r[j] = n0r; a0i[j] = n0i; a1r[j] = n1r; a1i[j] = n1i;
    }
}

__device__ __forceinline__ void gate_lo_2(int bbit, int lane, const float2* G,
                                          float* a0r, float* a0i, float* a1r, float* a1i) {
    const unsigned F = 0xffffffffu;
    float2 g00 = G[0], g01 = G[1], g10 = G[2], g11 = G[3];
    int m = 1 << bbit;
    bool hi = (lane >> bbit) & 1;
    float Ar = hi ? g11.x : g00.x, Ai = hi ? g11.y : g00.y;
    float Pr = hi ? g10.x : g01.x, Pi = hi ? g10.y : g01.y;
#pragma unroll
    for (int j = 0; j < 2; j++) {
        float p0r = __shfl_xor_sync(F, a0r[j], m);
        float p0i = __shfl_xor_sync(F, a0i[j], m);
        float p1r = __shfl_xor_sync(F, a1r[j], m);
        float p1i = __shfl_xor_sync(F, a1i[j], m);
        float n0r = Ar * a0r[j] - Ai * a0i[j] + Pr * p0r - Pi * p0i;
        float n0i = Ar * a0i[j] + Ai * a0r[j] + Pr * p0i + Pi * p0r;
        float n1r = Ar * a1r[j] - Ai * a1i[j] + Pr * p1r - Pi * p1i;
        float n1i = Ar * a1i[j] + Ai * a1r[j] + Pr * p1i + Pi * p1r;
        a0r[j] = n0r; a0i[j] = n0i; a1r[j] = n1r; a1i[j] = n1i;
    }
}

__device__ __forceinline__ int ring_src(int s) {
    int b5 = (s >> 5) & 1, b4 = (s >> 4) & 1, b3 = (s >> 3) & 1;
    int b2 = (s >> 2) & 1, b1 = (s >> 1) & 1, b0 = s & 1;
    b5 ^= b0; b0 ^= b1; b1 ^= b2; b2 ^= b3; b3 ^= b4; b4 ^= b5;
    return (b5 << 5) | (b4 << 4) | (b3 << 3) | (b2 << 2) | (b1 << 1) | b0;
}

__device__ __forceinline__ void ring2_2(int q0l, int q0h, int q1l, int q1h,
                                        float* a0r, float* a0i, float* a1r, float* a1i) {
    const unsigned F = 0xffffffffu;
#pragma unroll
    for (int j = 0; j < 2; j++) {
        float x0r = __shfl_sync(F, a0r[j], q0l);
        float y0r = __shfl_sync(F, a1r[j], q0l);
        float x0i = __shfl_sync(F, a0i[j], q0l);
        float y0i = __shfl_sync(F, a1i[j], q0l);
        float x1r = __shfl_sync(F, a0r[j], q1l);
        float y1r = __shfl_sync(F, a1r[j], q1l);
        float x1i = __shfl_sync(F, a0i[j], q1l);
        float y1i = __shfl_sync(F, a1i[j], q1l);
        a0r[j] = q0h ? y0r : x0r; a0i[j] = q0h ? y0i : x0i;
        a1r[j] = q1h ? y1r : x1r; a1i[j] = q1h ? y1i : x1i;
    }
}

// ---------------- prep (grid 163, overlapped via PDL) ----------------
// block 0: circuit unitary B1 + Wq'. blocks 1..162: conv weight fragments d_Wrf.
__global__ void k_prep(const float* __restrict__ qcnn, const float* __restrict__ meas,
                       const float* __restrict__ ow, const float* __restrict__ wr,
                       const float* __restrict__ wd) {
    cudaTriggerProgrammaticLaunchCompletion();
    int tid = threadIdx.x;

    if (blockIdx.x > 0) {
        // conv weight fragments: element i of d_Wrf
        int i = (blockIdx.x - 1) * 256 + tid;   // 162*256 = 41472 exactly
        int half = i & 1;
        int r = i >> 1;
        int lane = r & 31; r >>= 5;
        int nt = r % 9; r /= 9;
        int kt = r % 9; r /= 9;
        int chunk = r;                          // 0..7
        int n = nt * 8 + (lane >> 2);
        int k = chunk * 72 + kt * 8 + (half << 2) + (lane & 3);
        float val = 0.f;
        if (n < 64) val = __ldg(wr + n * 576 + k);
        else if (n < 70) val = __ldg(wd + (n - 64) * 576 + k);
        d_Wrf[i] = __uint_as_float(f2tf32(val));
        return;
    }

    __shared__ float2 s_g1[6][4], s_g2[6][4];
    __shared__ float s_b0[6];
    int lane = tid & 31, warp = tid >> 5;

    if (tid < 6) {
        int i = tid;
        float b0 = qcnn[i * 6 + 3];
        s_b0[i] = b0;
        float a1 = qcnn[36 + i * 6];
        float b1 = qcnn[36 + i * 6 + 3];
        float ca = cosf(0.5f * a1), sa = sinf(0.5f * a1);
        float cb = cosf(0.5f * b1), sbv = sinf(0.5f * b1);
        s_g1[i][0] = make_float2(cb * ca, -sbv * ca);
        s_g1[i][1] = make_float2(-cb * sa, sbv * sa);
        s_g1[i][2] = make_float2(cb * sa, sbv * sa);
        s_g1[i][3] = make_float2(cb * ca, sbv * ca);
        float th = meas[i * 3 + 0], phv = meas[i * 3 + 1], la = meas[i * 3 + 2];
        float ct = cosf(0.5f * th), st = sinf(0.5f * th);
        s_g2[i][0] = make_float2(ct, 0.f);
        s_g2[i][1] = make_float2(-cosf(la) * st, -sinf(la) * st);
        s_g2[i][2] = make_float2(cosf(phv) * st, sinf(phv) * st);
        s_g2[i][3] = make_float2(cosf(phv + la) * ct, sinf(phv + la) * ct);
    }
    __syncthreads();

    int q0 = ring_src(lane), q1 = ring_src(lane + 32);
    int q0l = q0 & 31, q0h = q0 >> 5;
    int q1l = q1 & 31, q1h = q1 >> 5;

    for (int q = 0; q < 4; q++) {
        int tcol[2] = {(warp * 4 + q) * 2, (warp * 4 + q) * 2 + 1};
        float a0r[2], a0i[2], a1r[2], a1i[2];
#pragma unroll
        for (int j = 0; j < 2; j++) {
            float th = 0.f;
#pragma unroll
            for (int i = 0; i < 6; i++)
                if ((tcol[j] >> (5 - i)) & 1) th += s_b0[i];
            float sv, cv;
            __sincosf(th, &sv, &cv);
            a0r[j] = (lane == tcol[j]) ? cv : 0.f;
            a0i[j] = (lane == tcol[j]) ? sv : 0.f;
            a1r[j] = (lane + 32 == tcol[j]) ? cv : 0.f;
            a1i[j] = (lane + 32 == tcol[j]) ? sv : 0.f;
        }
        ring2_2(q0l, q0h, q1l, q1h, a0r, a0i, a1r, a1i);
#pragma unroll
        for (int i = 0; i < 6; i++) {
            if (i == 0) gate_b5_2(s_g1[0], a0r, a0i, a1r, a1i);
            else        gate_lo_2(5 - i, lane, s_g1[i], a0r, a0i, a1r, a1i);
        }
        ring2_2(q0l, q0h, q1l, q1h, a0r, a0i, a1r, a1i);
#pragma unroll
        for (int i = 0; i < 6; i++) {
            if (i == 0) gate_b5_2(s_g2[0], a0r, a0i, a1r, a1i);
            else        gate_lo_2(5 - i, lane, s_g2[i], a0r, a0i, a1r, a1i);
        }
#pragma unroll
        for (int j = 0; j < 2; j++) {
            int k = tcol[j];
            d_B1f[fidxB1(k, lane)]          = __uint_as_float(f2tf32(a0r[j]));
            d_B1f[fidxB1(k, 64 + lane)]     = __uint_as_float(f2tf32(a0i[j]));
            d_B1f[fidxB1(k, lane + 32)]     = __uint_as_float(f2tf32(a1r[j]));
            d_B1f[fidxB1(k, 96 + lane)]     = __uint_as_float(f2tf32(a1i[j]));
        }
    }
    for (int i = tid; i < 4096; i += 256) {
        int s = i >> 6, co = i & 63;
        float acc = 0.f;
#pragma unroll
        for (int w = 0; w < 6; w++)
            acc += ow[co * 6 + w] * (((s >> (5 - w)) & 1) ? -1.f : 1.f);
        d_Wqf[fidxWq(s, co)] = __uint_as_float(f2tf32(acc));
    }
}

// ---------------- fused kernel ----------------
// R13 skeleton. Chunk 0: B from smB (staged in-kernel, pre-PDL-safe).
// Chunks 1-7: B fragments directly from L2 (d_Wrf, prep-written, PDL-gated at chunk 1).
// dyn smem: mainloop [xs 8448 | smB 20736]; tail: [stg 33280 @0 | PSI @33280]
#define SMB_OFF 8448
#define PSI_OFF 33280
#define FUSED_SMEM 66560

__global__ __launch_bounds__(256, 2) void k_fused(
    const float* __restrict__ x, const float* __restrict__ wr,
    const float* __restrict__ wd, const float* __restrict__ rb,
    const float* __restrict__ db, const float* __restrict__ style,
    const float* __restrict__ sw, const float* __restrict__ sb,
    const float* __restrict__ qcnn, const float* __restrict__ ob,
    float* __restrict__ out) {
    extern __shared__ char smem[];
    uint32_t* xs_u = (uint32_t*)smem;                  // x tile, tf32 bits, linear 2112
    char* smB = smem + SMB_OFF;                        // chunk-0 B frags
    __shared__ float s_phiadd[6];
    __shared__ float2 scs[8][96];                      // [warp][px*6+wire] (cos,sin)
    __shared__ float sphi_all[8][96];                  // [warp][16 px][6 wires]

    const unsigned F = 0xffffffffu;
    int tid = threadIdx.x;
    int lane = tid & 31;
    int wid = tid >> 5;               // warp = m-tile
    int g = lane >> 2, t4 = lane & 3;
    int px0 = blockIdx.x << 7;
    int b = px0 >> 12;
    int hwbase = px0 & 4095;
    int h0 = hwbase >> 6;

    if (wid < 6) {   // style projection, wire = wid
        float4 a = reinterpret_cast<const float4*>(style + b * 128)[lane];
        float4 w = reinterpret_cast<const float4*>(sw + wid * 128)[lane];
        float acc0 = a.x * w.x + a.y * w.y + a.z * w.z + a.w * w.w;
#pragma unroll
        for (int o = 16; o; o >>= 1) acc0 += __shfl_xor_sync(F, acc0, o);
        if (lane == 0)
            s_phiadd[wid] = PI_F * tanhf(acc0 + sb[wid]) + qcnn[wid * 6];
    }

    // --- A-offset table (chunk-invariant) ---
    int offs[18];
#pragma unroll
    for (int kk2 = 0; kk2 < 18; kk2++) {
        int kt = kk2 >> 1, half = kk2 & 1;
        int kloc = kt * 8 + 4 * half + t4;
        int ci = kloc / 9, kr = kloc - ci * 9;
        offs[kk2] = ci * 264 + (kr / 3) * 66 + (kr - (kr / 3) * 3);
    }
    int base0 = (wid >> 2) * 66 + (wid & 3) * 16 + g;

    float acc[9][4];
#pragma unroll
    for (int j = 0; j < 9; j++)
#pragma unroll
        for (int c = 0; c < 4; c++) acc[j][c] = 0.f;

    float px_x[9];

    // --- prefetch chunk 0 x ---
#pragma unroll
    for (int it = 0; it < 9; it++) {
        int j = tid + (it << 8);
        float v = 0.f;
        if (it < 8 || tid < 64) {
            int ci = j / 264, rem = j - ci * 264;
            int r = rem / 66, cpos = rem - r * 66;
            int gh = h0 - 1 + r, gw = cpos - 1;
            if ((unsigned)gh < 64u && (unsigned)gw < 64u)
                v = __ldg(x + (((b << 6) + ci) << 12) + (gh << 6) + gw);
        }
        px_x[it] = v;
    }
    // --- stage chunk-0 weights into smB (only chunk staged in-kernel) ---
    for (int i = tid; i < 1260; i += 256) {
        int n = i / 18, qf = i - n * 18;
        const float* src = (n < 64) ? (wr + n * 576) : (wd + (n - 64) * 576);
        float4 v = *reinterpret_cast<const float4*>(src + (qf << 2));
        int kt = qf >> 1, half = qf & 1;
        uint32_t* dst = reinterpret_cast<uint32_t*>(smB) +
                        (((kt * 9 + (n >> 3)) * 32 + ((n & 7) << 2)) << 1) + half;
        dst[0] = f2tf32(v.x);
        dst[2] = f2tf32(v.y);
        dst[4] = f2tf32(v.z);
        dst[6] = f2tf32(v.w);
    }

    // --- pipelined mainloop ---
    for (int chunk = 0; chunk < 8; chunk++) {
        if (chunk) __syncthreads();
#pragma unroll
        for (int it = 0; it < 9; it++) {
            if (it < 8 || tid < 64)
                xs_u[tid + (it << 8)] = f2tf32(px_x[it]);
        }
        __syncthreads();
        if (chunk == 1)
            cudaGridDependencySynchronize();   // PDL: prep done before d_Wrf reads
        if (chunk < 7) {
            int cn = chunk + 1;
#pragma unroll
            for (int it = 0; it < 9; it++) {
                int j = tid + (it << 8);
                float v = 0.f;
                if (it < 8 || tid < 64) {
                    int ci = j / 264, rem = j - ci * 264;
                    int r = rem / 66, cpos = rem - r * 66;
                    int gh = h0 - 1 + r, gw = cpos - 1;
                    if ((unsigned)gh < 64u && (unsigned)gw < 64u)
                        v = __ldg(x + (((b << 6) + (cn << 3) + ci) << 12) + (gh << 6) + gw);
                }
                px_x[it] = v;
            }
        }
        if (chunk == 0) {
            // B from smem (staged above)
#pragma unroll
            for (int kt = 0; kt < 9; kt++) {
                uint32_t A[4];
                A[0] = xs_u[offs[2 * kt] + base0];
                A[1] = xs_u[offs[2 * kt] + base0 + 8];
                A[2] = xs_u[offs[2 * kt + 1] + base0];
                A[3] = xs_u[offs[2 * kt + 1] + base0 + 8];
#pragma unroll
                for (int nt = 0; nt < 9; nt++) {
                    uint2 bb = *reinterpret_cast<const uint2*>(
                        smB + ((kt * 9 + nt) * 32 + lane) * 8);
                    uint32_t B[2] = {bb.x, bb.y};
                    mma8(acc[nt], A, B);
                }
            }
        } else {
            // B from L2 fragment table
            const float* wf = d_Wrf + chunk * 5184;
#pragma unroll
            for (int kt = 0; kt < 9; kt++) {
                uint32_t A[4];
                A[0] = xs_u[offs[2 * kt] + base0];
                A[1] = xs_u[offs[2 * kt] + base0 + 8];
                A[2] = xs_u[offs[2 * kt + 1] + base0];
                A[3] = xs_u[offs[2 * kt + 1] + base0 + 8];
#pragma unroll
                for (int nt = 0; nt < 9; nt++) {
                    uint2 bb = *reinterpret_cast<const uint2*>(
                        wf + (((kt * 9 + nt) * 32 + lane) << 1));
                    uint32_t B[2] = {bb.x, bb.y};
                    mma8(acc[nt], A, B);
                }
            }
        }
    }
    __syncthreads();   // mma done; mainloop smem regions reusable

    float* stg = (float*)smem;                         // [128][65]
    uint32_t* PSIu = (uint32_t*)(smem + PSI_OFF);      // [128][65]

    // --- phi -> sphi ; conv epilogue -> stg ---
    float* sphi = sphi_all[wid];
    if (t4 < 3) {
#pragma unroll
        for (int c = 0; c < 4; c++) {
            int pxl = g + 8 * (c >> 1);
            int wire = 2 * t4 + (c & 1);
            sphi[pxl * 6 + wire] =
                PI_F * tanhf(acc[8][c] + __ldg(db + wire)) + s_phiadd[wire];
        }
    }
#pragma unroll
    for (int nt = 0; nt < 8; nt++) {
#pragma unroll
        for (int c = 0; c < 4; c++) {
            int pxl = g + 8 * (c >> 1);
            int co = nt * 8 + 2 * t4 + (c & 1);
            stg[(wid * 16 + pxl) * 65 + co] = acc[nt][c] + __ldg(rb + co);
        }
    }
    __syncwarp();

    // --- cos/sin(phi/2) per (px, wire): 3 sincos per lane ---
#pragma unroll
    for (int r = 0; r < 3; r++) {
        int idx = lane + (r << 5);
        float ph = sphi[idx];
        float sv, cv;
        __sincosf(0.5f * ph, &sv, &cv);
        scs[wid][idx] = make_float2(cv, sv);
    }
    __syncwarp();

    // --- build real product state PSI[px][64] (tf32 bits) ---
    for (int pxl = 0; pxl < 16; pxl++) {
        float2 c0 = scs[wid][pxl * 6 + 0];
        float m = 1.f;
#pragma unroll
        for (int i = 1; i < 6; i++) {
            float2 ci = scs[wid][pxl * 6 + i];
            m *= ((lane >> (5 - i)) & 1) ? ci.y : ci.x;
        }
        int row = (wid * 16 + pxl) * 65;
        PSIu[row + lane] = f2tf32(c0.x * m);
        PSIu[row + lane + 32] = f2tf32(c0.y * m);
    }
    __syncwarp();

    // --- GEMM1: D1[px][128] = PSI[px][64] x B1 (B frags from L2) ---
    float acc1[16][4];
#pragma unroll
    for (int j = 0; j < 16; j++)
#pragma unroll
        for (int c = 0; c < 4; c++) acc1[j][c] = 0.f;
    {
        int abase = (wid * 16 + g) * 65 + t4;
#pragma unroll
        for (int kt = 0; kt < 8; kt++) {
            uint32_t A[4];
            A[0] = PSIu[abase + kt * 8];
            A[1] = PSIu[abase + kt * 8 + 8 * 65];
            A[2] = PSIu[abase + kt * 8 + 4];
            A[3] = PSIu[abase + kt * 8 + 4 + 8 * 65];
#pragma unroll
            for (int nt = 0; nt < 16; nt++) {
                uint2 bb = *reinterpret_cast<const uint2*>(
                    d_B1f + (((kt * 16 + nt) * 32 + lane) << 1));
                uint32_t B[2] = {bb.x, bb.y};
                mma8(acc1[nt], A, B);
            }
        }
    }
    // --- probs into PSI region (own rows only) ---
#pragma unroll
    for (int nt = 0; nt < 8; nt++) {
#pragma unroll
        for (int c = 0; c < 4; c++) {
            float p = acc1[nt][c] * acc1[nt][c] + acc1[nt + 8][c] * acc1[nt + 8][c];
            int s = nt * 8 + 2 * t4 + (c & 1);
            int pxg = wid * 16 + g + 8 * (c >> 1);
            PSIu[pxg * 65 + s] = f2tf32(p);
        }
    }
    __syncwarp();

    // --- GEMM2: D2[px][64co] = p[px][64] x Wq' (B frags from L2) ---
    float acc2[8][4];
#pragma unroll
    for (int j = 0; j < 8; j++)
#pragma unroll
        for (int c = 0; c < 4; c++) acc2[j][c] = 0.f;
    {
        int abase = (wid * 16 + g) * 65 + t4;
#pragma unroll
        for (int kt = 0; kt < 8; kt++) {
            uint32_t A[4];
            A[0] = PSIu[abase + kt * 8];
            A[1] = PSIu[abase + kt * 8 + 8 * 65];
            A[2] = PSIu[abase + kt * 8 + 4];
            A[3] = PSIu[abase + kt * 8 + 4 + 8 * 65];
#pragma unroll
            for (int nt = 0; nt < 8; nt++) {
                uint2 bb = *reinterpret_cast<const uint2*>(
                    d_Wqf + (((kt * 8 + nt) * 32 + lane) << 1));
                uint32_t B[2] = {bb.x, bb.y};
                mma8(acc2[nt], A, B);
            }
        }
    }
    // --- merge quant output + bias into stg ---
#pragma unroll
    for (int nt = 0; nt < 8; nt++) {
#pragma unroll
        for (int c = 0; c < 4; c++) {
            int co = nt * 8 + 2 * t4 + (c & 1);
            int pxg = wid * 16 + g + 8 * (c >> 1);
            stg[pxg * 65 + co] += acc2[nt][c] + __ldg(ob + co);
        }
    }
    __syncthreads();

    // --- fully coalesced final write ---
    for (int i = tid; i < 8192; i += 256) {
        int co = i >> 7, px = i & 127;
        out[(((b << 6) + co) << 12) + hwbase + px] = stg[px * 65 + co];
    }
}

// ---------------- launch ----------------
extern "C" void kernel_launch(void* const* d_in, const int* in_sizes, int n_in,
                              void* d_out, int out_size) {
    const float* x     = (const float*)d_in[0];
    const float* style = (const float*)d_in[1];
    const float* wd    = (const float*)d_in[2];   // data_proj_w [6,576]
    const float* db    = (const float*)d_in[3];   // data_proj_b [6]
    const float* sw    = (const float*)d_in[4];   // style_to_data_w [6,128]
    const float* sb    = (const float*)d_in[5];   // style_to_data_b [6]
    const float* qcnn  = (const float*)d_in[6];   // [2,6,2,3]
    const float* meas  = (const float*)d_in[7];   // [6,3]
    const float* ow    = (const float*)d_in[8];   // out_proj_w [64,6]
    const float* ob    = (const float*)d_in[9];   // out_proj_b [64]
    const float* wr    = (const float*)d_in[10];  // res_proj_w [64,576]
    const float* rb    = (const float*)d_in[11];  // res_proj_b [64]
    float* out = (float*)d_out;

    cudaFuncSetAttribute(k_fused, cudaFuncAttributeMaxDynamicSharedMemorySize, FUSED_SMEM);

    k_prep<<<163, 256>>>(qcnn, meas, ow, wr, wd);

    // PDL: k_fused starts as soon as k_prep triggers launch completion (entry);
    // gates on k_prep's full completion at chunk 1 of the mainloop.
    cudaLaunchConfig_t cfg = {};
    cfg.gridDim = dim3(256, 1, 1);
    cfg.blockDim = dim3(256, 1, 1);
    cfg.dynamicSmemBytes = FUSED_SMEM;
    cfg.stream = 0;
    cudaLaunchAttribute attrs[1];
    attrs[0].id = cudaLaunchAttributeProgrammaticStreamSerialization;
    attrs[0].val.programmaticStreamSerializationAllowed = 1;
    cfg.attrs = attrs;
    cfg.numAttrs = 1;
    cudaLaunchKernelEx(&cfg, k_fused, x, wr, wd, rb, db, style, sw, sb, qcnn, ob, out);
}

// round 17
// speedup vs baseline: 3.0505x; 1.1535x over previous
#include <cuda_runtime.h>
#include <cstdint>

#define PI_F 3.14159265358979f

// ---------------- device-global tables (prep -> main) ----------------
__device__ float d_B1f[8192];    // B1[64k][128n] in mma B-frag layout, tf32
__device__ float d_Wqf[4096];    // Wq'[64k][64n] in mma B-frag layout, tf32
__device__ float d_Wrf[41472];   // conv weights [8 chunk][9 kt][9 nt][32 lane][2]

__device__ __forceinline__ uint32_t f2tf32(float f) {
    uint32_t r;
    asm("cvt.rna.tf32.f32 %0, %1;" : "=r"(r) : "f"(f));
    return r;
}

__device__ __forceinline__ uint32_t smem_u32(const void* p) {
    uint32_t a;
    asm("{ .reg .u64 t; cvta.to.shared.u64 t, %1; cvt.u32.u64 %0, t; }" : "=r"(a) : "l"(p));
    return a;
}

__device__ __forceinline__ void mma8(float* d, const uint32_t* a, const uint32_t* b) {
    asm volatile(
        "mma.sync.aligned.m16n8k8.row.col.f32.tf32.tf32.f32 "
        "{%0,%1,%2,%3}, {%4,%5,%6,%7}, {%8,%9}, {%0,%1,%2,%3};"
        : "+f"(d[0]), "+f"(d[1]), "+f"(d[2]), "+f"(d[3])
        : "r"(a[0]), "r"(a[1]), "r"(a[2]), "r"(a[3]), "r"(b[0]), "r"(b[1]));
}

// B-fragment storage index (float units) for element (k, n)
__device__ __forceinline__ int fidxB1(int k, int n) {   // 16 n-tiles
    return ((((k >> 3) * 16 + (n >> 3)) * 32 + (n & 7) * 4 + (k & 3)) << 1) + ((k >> 2) & 1);
}
__device__ __forceinline__ int fidxWq(int k, int n) {   // 8 n-tiles
    return ((((k >> 3) * 8 + (n >> 3)) * 32 + (n & 7) * 4 + (k & 3)) << 1) + ((k >> 2) & 1);
}

// ---------------- quantum gate helpers (2-state ILP, prep only) ----------------
__device__ __forceinline__ void gate_b5_2(const float2* G,
                                          float* a0r, float* a0i, float* a1r, float* a1i) {
    float2 g00 = G[0], g01 = G[1], g10 = G[2], g11 = G[3];
#pragma unroll
    for (int j = 0; j < 2; j++) {
        float n0r = g00.x * a0r[j] - g00.y * a0i[j] + g01.x * a1r[j] - g01.y * a1i[j];
        float n0i = g00.x * a0i[j] + g00.y * a0r[j] + g01.x * a1i[j] + g01.y * a1r[j];
        float n1r = g10.x * a0r[j] - g10.y * a0i[j] + g11.x * a1r[j] - g11.y * a1i[j];
        float n1i = g10.x * a0i[j] + g10.y * a0r[j] + g11.x * a1i[j] + g11.y * a1r[j];
        a0r[j] = n0r; a0i[j] = n0i; a1r[j] = n1r; a1i[j] = n1i;
    }
}

__device__ __forceinline__ void gate_lo_2(int bbit, int lane, const float2* G,
                                          float* a0r, float* a0i, float* a1r, float* a1i) {
    const unsigned F = 0xffffffffu;
    float2 g00 = G[0], g01 = G[1], g10 = G[2], g11 = G[3];
    int m = 1 << bbit;
    bool hi = (lane >> bbit) & 1;
    float Ar = hi ? g11.x : g00.x, Ai = hi ? g11.y : g00.y;
    float Pr = hi ? g10.x : g01.x, Pi = hi ? g10.y : g01.y;
#pragma unroll
    for (int j = 0; j < 2; j++) {
        float p0r = __shfl_xor_sync(F, a0r[j], m);
        float p0i = __shfl_xor_sync(F, a0i[j], m);
        float p1r = __shfl_xor_sync(F, a1r[j], m);
        float p1i = __shfl_xor_sync(F, a1i[j], m);
        float n0r = Ar * a0r[j] - Ai * a0i[j] + Pr * p0r - Pi * p0i;
        float n0i = Ar * a0i[j] + Ai * a0r[j] + Pr * p0i + Pi * p0r;
        float n1r = Ar * a1r[j] - Ai * a1i[j] + Pr * p1r - Pi * p1i;
        float n1i = Ar * a1i[j] + Ai * a1r[j] + Pr * p1i + Pi * p1r;
        a0r[j] = n0r; a0i[j] = n0i; a1r[j] = n1r; a1i[j] = n1i;
    }
}

__device__ __forceinline__ int ring_src(int s) {
    int b5 = (s >> 5) & 1, b4 = (s >> 4) & 1, b3 = (s >> 3) & 1;
    int b2 = (s >> 2) & 1, b1 = (s >> 1) & 1, b0 = s & 1;
    b5 ^= b0; b0 ^= b1; b1 ^= b2; b2 ^= b3; b3 ^= b4; b4 ^= b5;
    return (b5 << 5) | (b4 << 4) | (b3 << 3) | (b2 << 2) | (b1 << 1) | b0;
}

__device__ __forceinline__ void ring2_2(int q0l, int q0h, int q1l, int q1h,
                                        float* a0r, float* a0i, float* a1r, float* a1i) {
    const unsigned F = 0xffffffffu;
#pragma unroll
    for (int j = 0; j < 2; j++) {
        float x0r = __shfl_sync(F, a0r[j], q0l);
        float y0r = __shfl_sync(F, a1r[j], q0l);
        float x0i = __shfl_sync(F, a0i[j], q0l);
        float y0i = __shfl_sync(F, a1i[j], q0l);
        float x1r = __shfl_sync(F, a0r[j], q1l);
        float y1r = __shfl_sync(F, a1r[j], q1l);
        float x1i = __shfl_sync(F, a0i[j], q1l);
        float y1i = __shfl_sync(F, a1i[j], q1l);
        a0r[j] = q0h ? y0r : x0r; a0i[j] = q0h ? y0i : x0i;
        a1r[j] = q1h ? y1r : x1r; a1i[j] = q1h ? y1i : x1i;
    }
}

// ---------------- prep (grid 163, overlapped via PDL) ----------------
__global__ void k_prep(const float* __restrict__ qcnn, const float* __restrict__ meas,
                       const float* __restrict__ ow, const float* __restrict__ wr,
                       const float* __restrict__ wd) {
    cudaTriggerProgrammaticLaunchCompletion();
    int tid = threadIdx.x;

    if (blockIdx.x > 0) {
        int i = (blockIdx.x - 1) * 256 + tid;   // 162*256 = 41472 exactly
        int half = i & 1;
        int r = i >> 1;
        int lane = r & 31; r >>= 5;
        int nt = r % 9; r /= 9;
        int kt = r % 9; r /= 9;
        int chunk = r;
        int n = nt * 8 + (lane >> 2);
        int k = chunk * 72 + kt * 8 + (half << 2) + (lane & 3);
        float val = 0.f;
        if (n < 64) val = __ldg(wr + n * 576 + k);
        else if (n < 70) val = __ldg(wd + (n - 64) * 576 + k);
        d_Wrf[i] = __uint_as_float(f2tf32(val));
        return;
    }

    __shared__ float2 s_g1[6][4], s_g2[6][4];
    __shared__ float s_b0[6];
    int lane = tid & 31, warp = tid >> 5;

    if (tid < 6) {
        int i = tid;
        float b0 = qcnn[i * 6 + 3];
        s_b0[i] = b0;
        float a1 = qcnn[36 + i * 6];
        float b1 = qcnn[36 + i * 6 + 3];
        float ca = cosf(0.5f * a1), sa = sinf(0.5f * a1);
        float cb = cosf(0.5f * b1), sbv = sinf(0.5f * b1);
        s_g1[i][0] = make_float2(cb * ca, -sbv * ca);
        s_g1[i][1] = make_float2(-cb * sa, sbv * sa);
        s_g1[i][2] = make_float2(cb * sa, sbv * sa);
        s_g1[i][3] = make_float2(cb * ca, sbv * ca);
        float th = meas[i * 3 + 0], phv = meas[i * 3 + 1], la = meas[i * 3 + 2];
        float ct = cosf(0.5f * th), st = sinf(0.5f * th);
        s_g2[i][0] = make_float2(ct, 0.f);
        s_g2[i][1] = make_float2(-cosf(la) * st, -sinf(la) * st);
        s_g2[i][2] = make_float2(cosf(phv) * st, sinf(phv) * st);
        s_g2[i][3] = make_float2(cosf(phv + la) * ct, sinf(phv + la) * ct);
    }
    __syncthreads();

    int q0 = ring_src(lane), q1 = ring_src(lane + 32);
    int q0l = q0 & 31, q0h = q0 >> 5;
    int q1l = q1 & 31, q1h = q1 >> 5;

    for (int q = 0; q < 4; q++) {
        int tcol[2] = {(warp * 4 + q) * 2, (warp * 4 + q) * 2 + 1};
        float a0r[2], a0i[2], a1r[2], a1i[2];
#pragma unroll
        for (int j = 0; j < 2; j++) {
            float th = 0.f;
#pragma unroll
            for (int i = 0; i < 6; i++)
                if ((tcol[j] >> (5 - i)) & 1) th += s_b0[i];
            float sv, cv;
            __sincosf(th, &sv, &cv);
            a0r[j] = (lane == tcol[j]) ? cv : 0.f;
            a0i[j] = (lane == tcol[j]) ? sv : 0.f;
            a1r[j] = (lane + 32 == tcol[j]) ? cv : 0.f;
            a1i[j] = (lane + 32 == tcol[j]) ? sv : 0.f;
        }
        ring2_2(q0l, q0h, q1l, q1h, a0r, a0i, a1r, a1i);
#pragma unroll
        for (int i = 0; i < 6; i++) {
            if (i == 0) gate_b5_2(s_g1[0], a0r, a0i, a1r, a1i);
            else        gate_lo_2(5 - i, lane, s_g1[i], a0r, a0i, a1r, a1i);
        }
        ring2_2(q0l, q0h, q1l, q1h, a0r, a0i, a1r, a1i);
#pragma unroll
        for (int i = 0; i < 6; i++) {
            if (i == 0) gate_b5_2(s_g2[0], a0r, a0i, a1r, a1i);
            else        gate_lo_2(5 - i, lane, s_g2[i], a0r, a0i, a1r, a1i);
        }
#pragma unroll
        for (int j = 0; j < 2; j++) {
            int k = tcol[j];
            d_B1f[fidxB1(k, lane)]          = __uint_as_float(f2tf32(a0r[j]));
            d_B1f[fidxB1(k, 64 + lane)]     = __uint_as_float(f2tf32(a0i[j]));
            d_B1f[fidxB1(k, lane + 32)]     = __uint_as_float(f2tf32(a1r[j]));
            d_B1f[fidxB1(k, 96 + lane)]     = __uint_as_float(f2tf32(a1i[j]));
        }
    }
    for (int i = tid; i < 4096; i += 256) {
        int s = i >> 6, co = i & 63;
        float acc = 0.f;
#pragma unroll
        for (int w = 0; w < 6; w++)
            acc += ow[co * 6 + w] * (((s >> (5 - w)) & 1) ? -1.f : 1.f);
        d_Wqf[fidxWq(s, co)] = __uint_as_float(f2tf32(acc));
    }
}

// ---------------- fused kernel ----------------
// R15 skeleton with cp.async double-buffered x staging.
// xs buffers: [8 ci][4 rows][72 floats]; interior (gw 0..63) at cpos 4..67;
// zeros at cpos 3 / 68 and invalid rows (pre-filled once, chunk-invariant).
// dyn smem: mainloop [xsA 9216 | xsB 9216 | smB 20736]=39168;
// tail: [stg 33280 @0 | PSI @33280] (total 66560)
#define XSB_OFF 9216
#define SMB_OFF 18432
#define PSI_OFF 33280
#define FUSED_SMEM 66560

__global__ __launch_bounds__(256, 2) void k_fused(
    const float* __restrict__ x, const float* __restrict__ wr,
    const float* __restrict__ wd, const float* __restrict__ rb,
    const float* __restrict__ db, const float* __restrict__ style,
    const float* __restrict__ sw, const float* __restrict__ sb,
    const float* __restrict__ qcnn, const float* __restrict__ ob,
    float* __restrict__ out) {
    extern __shared__ char smem[];
    char* smB = smem + SMB_OFF;                        // chunk-0 B frags
    __shared__ float s_phiadd[6];
    __shared__ float2 scs[8][96];
    __shared__ float sphi_all[8][96];

    const unsigned F = 0xffffffffu;
    int tid = threadIdx.x;
    int lane = tid & 31;
    int wid = tid >> 5;               // warp = m-tile
    int g = lane >> 2, t4 = lane & 3;
    int px0 = blockIdx.x << 7;
    int b = px0 >> 12;
    int hwbase = px0 & 4095;
    int h0 = hwbase >> 6;
    uint32_t smem_base = smem_u32(smem);

    if (wid < 6) {   // style projection, wire = wid
        float4 a = reinterpret_cast<const float4*>(style + b * 128)[lane];
        float4 w = reinterpret_cast<const float4*>(sw + wid * 128)[lane];
        float acc0 = a.x * w.x + a.y * w.y + a.z * w.z + a.w * w.w;
#pragma unroll
        for (int o = 16; o; o >>= 1) acc0 += __shfl_xor_sync(F, acc0, o);
        if (lane == 0)
            s_phiadd[wid] = PI_F * tanhf(acc0 + sb[wid]) + qcnn[wid * 6];
    }

    // --- A-offset table (chunk-invariant); row stride 72, ci stride 288 ---
    int offs[18];
#pragma unroll
    for (int kk2 = 0; kk2 < 18; kk2++) {
        int kt = kk2 >> 1, half = kk2 & 1;
        int kloc = kt * 8 + 4 * half + t4;
        int ci = kloc / 9, kr = kloc - ci * 9;
        offs[kk2] = ci * 288 + (kr / 3) * 72 + (kr - (kr / 3) * 3);
    }
    int base0 = (wid >> 2) * 72 + (wid & 3) * 16 + g + 3;

    float acc[9][4];
#pragma unroll
    for (int j = 0; j < 9; j++)
#pragma unroll
        for (int c = 0; c < 4; c++) acc[j][c] = 0.f;

    // --- pre-zero both xs buffers (halo zeros are chunk-invariant) ---
    {
        uint32_t* z = (uint32_t*)smem;
        for (int i = tid; i < 4608; i += 256) z[i] = 0u;
    }
    // precompute the per-thread copy descriptors (2 ops/thread)
    int cp_dst[2];           // byte offset within buffer
    const float* cp_src0[2]; // chunk-0 src (advance by 8<<12 floats per chunk)
    bool cp_ok[2];
#pragma unroll
    for (int u = 0; u < 2; u++) {
        int o = tid + (u << 8);
        int row = o >> 4, seg = o & 15;
        int ci = row >> 2, r = row & 3;
        int gh = h0 - 1 + r;
        cp_ok[u] = ((unsigned)gh < 64u);
        cp_dst[u] = (ci * 288 + r * 72 + 4 + seg * 4) << 2;
        cp_src0[u] = x + (((b << 6) + ci) << 12) + (gh << 6) + seg * 4;
    }
    __syncthreads();   // zeros visible to ALL threads before any cp.async lands

    // issue chunk-0 copies into buffer 0
#pragma unroll
    for (int u = 0; u < 2; u++) {
        if (cp_ok[u])
            asm volatile("cp.async.cg.shared.global [%0], [%1], 16;"
                         :: "r"(smem_base + cp_dst[u]), "l"(cp_src0[u]));
    }
    asm volatile("cp.async.commit_group;" ::: "memory");

    // --- stage chunk-0 weights into smB ---
    for (int i = tid; i < 1260; i += 256) {
        int n = i / 18, qf = i - n * 18;
        const float* src = (n < 64) ? (wr + n * 576) : (wd + (n - 64) * 576);
        float4 v = *reinterpret_cast<const float4*>(src + (qf << 2));
        int kt = qf >> 1, half = qf & 1;
        uint32_t* dst = reinterpret_cast<uint32_t*>(smB) +
                        (((kt * 9 + (n >> 3)) * 32 + ((n & 7) << 2)) << 1) + half;
        dst[0] = f2tf32(v.x);
        dst[2] = f2tf32(v.y);
        dst[4] = f2tf32(v.z);
        dst[6] = f2tf32(v.w);
    }

    // --- mainloop: 1 barrier per chunk, cp.async overlapped with mma ---
    for (int chunk = 0; chunk < 8; chunk++) {
        asm volatile("cp.async.wait_group 0;" ::: "memory");
        __syncthreads();
        if (chunk == 1)
            cudaGridDependencySynchronize();   // PDL: prep done before d_Wrf reads
        if (chunk < 7) {
            // issue chunk+1 copies into the other buffer (overlaps mma below)
            uint32_t bb2 = smem_base + ((chunk + 1) & 1) * XSB_OFF;
            long srcoff = (long)(chunk + 1) * (8 << 12);
#pragma unroll
            for (int u = 0; u < 2; u++) {
                if (cp_ok[u])
                    asm volatile("cp.async.cg.shared.global [%0], [%1], 16;"
                                 :: "r"(bb2 + cp_dst[u]), "l"(cp_src0[u] + srcoff));
            }
            asm volatile("cp.async.commit_group;" ::: "memory");
        }
        const float* xsf = (const float*)(smem + (chunk & 1) * XSB_OFF);
        if (chunk == 0) {
#pragma unroll
            for (int kt = 0; kt < 9; kt++) {
                uint32_t A[4];
                A[0] = f2tf32(xsf[offs[2 * kt] + base0]);
                A[1] = f2tf32(xsf[offs[2 * kt] + base0 + 8]);
                A[2] = f2tf32(xsf[offs[2 * kt + 1] + base0]);
                A[3] = f2tf32(xsf[offs[2 * kt + 1] + base0 + 8]);
#pragma unroll
                for (int nt = 0; nt < 9; nt++) {
                    uint2 bb = *reinterpret_cast<const uint2*>(
                        smB + ((kt * 9 + nt) * 32 + lane) * 8);
                    uint32_t B[2] = {bb.x, bb.y};
                    mma8(acc[nt], A, B);
                }
            }
        } else {
            const float* wf = d_Wrf + chunk * 5184;
#pragma unroll
            for (int kt = 0; kt < 9; kt++) {
                uint32_t A[4];
                A[0] = f2tf32(xsf[offs[2 * kt] + base0]);
                A[1] = f2tf32(xsf[offs[2 * kt] + base0 + 8]);
                A[2] = f2tf32(xsf[offs[2 * kt + 1] + base0]);
                A[3] = f2tf32(xsf[offs[2 * kt + 1] + base0 + 8]);
#pragma unroll
                for (int nt = 0; nt < 9; nt++) {
                    uint2 bb = *reinterpret_cast<const uint2*>(
                        wf + (((kt * 9 + nt) * 32 + lane) << 1));
                    uint32_t B[2] = {bb.x, bb.y};
                    mma8(acc[nt], A, B);
                }
            }
        }
    }
    __syncthreads();   // mma done; mainloop smem regions reusable

    float* stg = (float*)smem;                         // [128][65]
    uint32_t* PSIu = (uint32_t*)(smem + PSI_OFF);      // [128][65]

    // --- phi -> sphi ; conv epilogue -> stg ---
    float* sphi = sphi_all[wid];
    if (t4 < 3) {
#pragma unroll
        for (int c = 0; c < 4; c++) {
            int pxl = g + 8 * (c >> 1);
            int wire = 2 * t4 + (c & 1);
            sphi[pxl * 6 + wire] =
                PI_F * tanhf(acc[8][c] + __ldg(db + wire)) + s_phiadd[wire];
        }
    }
#pragma unroll
    for (int nt = 0; nt < 8; nt++) {
#pragma unroll
        for (int c = 0; c < 4; c++) {
            int pxl = g + 8 * (c >> 1);
            int co = nt * 8 + 2 * t4 + (c & 1);
            stg[(wid * 16 + pxl) * 65 + co] = acc[nt][c] + __ldg(rb + co);
        }
    }
    __syncwarp();

    // --- cos/sin(phi/2) per (px, wire): 3 sincos per lane ---
#pragma unroll
    for (int r = 0; r < 3; r++) {
        int idx = lane + (r << 5);
        float ph = sphi[idx];
        float sv, cv;
        __sincosf(0.5f * ph, &sv, &cv);
        scs[wid][idx] = make_float2(cv, sv);
    }
    __syncwarp();

    // --- build real product state PSI[px][64] (tf32 bits) ---
    for (int pxl = 0; pxl < 16; pxl++) {
        float2 c0 = scs[wid][pxl * 6 + 0];
        float m = 1.f;
#pragma unroll
        for (int i = 1; i < 6; i++) {
            float2 ci = scs[wid][pxl * 6 + i];
            m *= ((lane >> (5 - i)) & 1) ? ci.y : ci.x;
        }
        int row = (wid * 16 + pxl) * 65;
        PSIu[row + lane] = f2tf32(c0.x * m);
        PSIu[row + lane + 32] = f2tf32(c0.y * m);
    }
    __syncwarp();

    // --- GEMM1: D1[px][128] = PSI[px][64] x B1 (B frags from L2) ---
    float acc1[16][4];
#pragma unroll
    for (int j = 0; j < 16; j++)
#pragma unroll
        for (int c = 0; c < 4; c++) acc1[j][c] = 0.f;
    {
        int abase = (wid * 16 + g) * 65 + t4;
#pragma unroll
        for (int kt = 0; kt < 8; kt++) {
            uint32_t A[4];
            A[0] = PSIu[abase + kt * 8];
            A[1] = PSIu[abase + kt * 8 + 8 * 65];
            A[2] = PSIu[abase + kt * 8 + 4];
            A[3] = PSIu[abase + kt * 8 + 4 + 8 * 65];
#pragma unroll
            for (int nt = 0; nt < 16; nt++) {
                uint2 bb = *reinterpret_cast<const uint2*>(
                    d_B1f + (((kt * 16 + nt) * 32 + lane) << 1));
                uint32_t B[2] = {bb.x, bb.y};
                mma8(acc1[nt], A, B);
            }
        }
    }
    // --- probs into PSI region (own rows only) ---
#pragma unroll
    for (int nt = 0; nt < 8; nt++) {
#pragma unroll
        for (int c = 0; c < 4; c++) {
            float p = acc1[nt][c] * acc1[nt][c] + acc1[nt + 8][c] * acc1[nt + 8][c];
            int s = nt * 8 + 2 * t4 + (c & 1);
            int pxg = wid * 16 + g + 8 * (c >> 1);
            PSIu[pxg * 65 + s] = f2tf32(p);
        }
    }
    __syncwarp();

    // --- GEMM2: D2[px][64co] = p[px][64] x Wq' (B frags from L2) ---
    float acc2[8][4];
#pragma unroll
    for (int j = 0; j < 8; j++)
#pragma unroll
        for (int c = 0; c < 4; c++) acc2[j][c] = 0.f;
    {
        int abase = (wid * 16 + g) * 65 + t4;
#pragma unroll
        for (int kt = 0; kt < 8; kt++) {
            uint32_t A[4];
            A[0] = PSIu[abase + kt * 8];
            A[1] = PSIu[abase + kt * 8 + 8 * 65];
            A[2] = PSIu[abase + kt * 8 + 4];
            A[3] = PSIu[abase + kt * 8 + 4 + 8 * 65];
#pragma unroll
            for (int nt = 0; nt < 8; nt++) {
                uint2 bb = *reinterpret_cast<const uint2*>(
                    d_Wqf + (((kt * 8 + nt) * 32 + lane) << 1));
                uint32_t B[2] = {bb.x, bb.y};
                mma8(acc2[nt], A, B);
            }
        }
    }
    // --- merge quant output + bias into stg ---
#pragma unroll
    for (int nt = 0; nt < 8; nt++) {
#pragma unroll
        for (int c = 0; c < 4; c++) {
            int co = nt * 8 + 2 * t4 + (c & 1);
            int pxg = wid * 16 + g + 8 * (c >> 1);
            stg[pxg * 65 + co] += acc2[nt][c] + __ldg(ob + co);
        }
    }
    __syncthreads();

    // --- fully coalesced final write ---
    for (int i = tid; i < 8192; i += 256) {
        int co = i >> 7, px = i & 127;
        out[(((b << 6) + co) << 12) + hwbase + px] = stg[px * 65 + co];
    }
}

// ---------------- launch ----------------
extern "C" void kernel_launch(void* const* d_in, const int* in_sizes, int n_in,
                              void* d_out, int out_size) {
    const float* x     = (const float*)d_in[0];
    const float* style = (const float*)d_in[1];
    const float* wd    = (const float*)d_in[2];   // data_proj_w [6,576]
    const float* db    = (const float*)d_in[3];   // data_proj_b [6]
    const float* sw    = (const float*)d_in[4];   // style_to_data_w [6,128]
    const float* sb    = (const float*)d_in[5];   // style_to_data_b [6]
    const float* qcnn  = (const float*)d_in[6];   // [2,6,2,3]
    const float* meas  = (const float*)d_in[7];   // [6,3]
    const float* ow    = (const float*)d_in[8];   // out_proj_w [64,6]
    const float* ob    = (const float*)d_in[9];   // out_proj_b [64]
    const float* wr    = (const float*)d_in[10];  // res_proj_w [64,576]
    const float* rb    = (const float*)d_in[11];  // res_proj_b [64]
    float* out = (float*)d_out;

    cudaFuncSetAttribute(k_fused, cudaFuncAttributeMaxDynamicSharedMemorySize, FUSED_SMEM);

    k_prep<<<163, 256>>>(qcnn, meas, ow, wr, wd);

    cudaLaunchConfig_t cfg = {};
    cfg.gridDim = dim3(256, 1, 1);
    cfg.blockDim = dim3(256, 1, 1);
    cfg.dynamicSmemBytes = FUSED_SMEM;
    cfg.stream = 0;
    cudaLaunchAttribute attrs[1];
    attrs[0].id = cudaLaunchAttributeProgrammaticStreamSerialization;
    attrs[0].val.programmaticStreamSerializationAllowed = 1;
    cfg.attrs = attrs;
    cfg.numAttrs = 1;
    cudaLaunchKernelEx(&cfg, k_fused, x, wr, wd, rb, db, style, sw, sb, qcnn, ob, out);
}